// round 1
// baseline (speedup 1.0000x reference)
#include <cuda_runtime.h>
#include <cuda_bf16.h>

// Problem constants (shapes fixed by the dataset)
#define NV    4096          // N = H*W = 64*64
#define WW    64            // width
#define CAP   128           // per-row bucket capacity (Poisson(20) rows, max ~45)
#define NNZCM 81920         // 20*N
#define MLOC  2048
#define MIU   2048

// Scratch (static device globals — no allocation)
__device__ int   g_cnt[NV];
__device__ float g_rowsum[NV];
__device__ int   g_col[NV * CAP];
__device__ float g_val[NV * CAP];

// ---------------------------------------------------------------------------
// Reset per-row buckets (must happen every launch: determinism requirement)
__global__ void k_reset() {
    int i = blockIdx.x * blockDim.x + threadIdx.x;
    if (i < NV) { g_cnt[i] = 0; g_rowsum[i] = 0.0f; }
}

// ---------------------------------------------------------------------------
// Bucket CM COO entries by row, scaled by CM_weights[row]; accumulate rowsum.
__global__ void k_build_cm(const int* __restrict__ row,
                           const int* __restrict__ col,
                           const float* __restrict__ data,
                           const float* __restrict__ cmw) {
    int e = blockIdx.x * blockDim.x + threadIdx.x;
    if (e >= NNZCM) return;
    int r = row[e];
    int c = col[e];
    float v = data[e] * __ldg(&cmw[r]);
    int slot = atomicAdd(&g_cnt[r], 1);
    if (slot < CAP) {
        g_col[r * CAP + slot] = c;
        g_val[r * CAP + slot] = v;
    }
    atomicAdd(&g_rowsum[r], v);
}

// ---------------------------------------------------------------------------
// Lcm^T Lcm = sum_k outer(row_k, row_k).
// Row k of Lcm as an entry list: [(c_e, -v_e) for e in bucket] + [(k, rowsum_k)].
// All-pairs products over the raw list == outer product of the accumulated
// dense row (duplicates handled automatically by bilinearity).
__global__ void k_outer(float* __restrict__ A) {
    int k = blockIdx.x;
    __shared__ int   scol[CAP + 1];
    __shared__ float sval[CAP + 1];
    int n = g_cnt[k];
    if (n > CAP) n = CAP;
    for (int i = threadIdx.x; i < n; i += blockDim.x) {
        scol[i] = g_col[k * CAP + i];
        sval[i] = -g_val[k * CAP + i];
    }
    if (threadIdx.x == 0) { scol[n] = k; sval[n] = g_rowsum[k]; }
    __syncthreads();
    int m = n + 1;
    int total = m * m;
    for (int p = threadIdx.x; p < total; p += blockDim.x) {
        int i = p / m;
        int j = p - i * m;
        atomicAdd(&A[(size_t)scol[i] * NV + scol[j]], sval[i] * sval[j]);
    }
}

// ---------------------------------------------------------------------------
// LOC term: raw entries (r0, c_j, v) with r0 = inInd[m] + offs[0],
// c_j = inInd[m] + offs[j], v = LOC_flows[j,0,m] * LOC_weights[inInd[m]].
// A += Lmat where Lmat = diag(rowsum(Ws)) - Ws, Ws = 0.5(W + W^T):
//   per raw entry: A[r0,c] -= 0.5v ; A[c,r0] -= 0.5v ;
//                  A[r0,r0] += 0.5v ; A[c,c] += 0.5v.
__global__ void k_loc(float* __restrict__ A,
                      const int* __restrict__ inInd,
                      const float* __restrict__ flows,   // (9, 9, MLOC)
                      const float* __restrict__ locw) {
    int t = blockIdx.x * blockDim.x + threadIdx.x;
    if (t >= MLOC * 9) return;
    int m = t & (MLOC - 1);
    int j = t >> 11;                      // MLOC = 2048 = 1<<11
    const int offs[9] = { -1 - WW, -1, -1 + WW, -WW, 0, WW, 1 - WW, 1, 1 + WW };
    int base = inInd[m];
    int r0 = base + offs[0];
    int c  = base + offs[j];
    float v = flows[(size_t)j * 9 * MLOC + m] * __ldg(&locw[base]);
    float h = 0.5f * v;
    atomicAdd(&A[(size_t)r0 * NV + c], -h);
    atomicAdd(&A[(size_t)c  * NV + r0], -h);
    atomicAdd(&A[(size_t)r0 * NV + r0],  h);
    atomicAdd(&A[(size_t)c  * NV + c],   h);
}

// ---------------------------------------------------------------------------
// IU term: raw entries (r, neigh[m][j], IU_flows[m][j] * IU_weights[r]),
// same symmetrize+Laplacian fold as k_loc.
__global__ void k_iu(float* __restrict__ A,
                     const int* __restrict__ inInd,
                     const float* __restrict__ flows,    // (MIU, 5)
                     const int* __restrict__ neigh,      // (MIU, 5)
                     const float* __restrict__ iuw) {
    int t = blockIdx.x * blockDim.x + threadIdx.x;
    if (t >= MIU * 5) return;
    int m = t / 5;
    int j = t - m * 5;
    int r = inInd[m];
    int c = neigh[m * 5 + j];
    float v = flows[m * 5 + j] * __ldg(&iuw[r]);
    float h = 0.5f * v;
    atomicAdd(&A[(size_t)r * NV + c], -h);
    atomicAdd(&A[(size_t)c * NV + r], -h);
    atomicAdd(&A[(size_t)r * NV + r],  h);
    atomicAdd(&A[(size_t)c * NV + c],  h);
}

// ---------------------------------------------------------------------------
// Diagonal regularization + RHS b.
__global__ void k_diag(float* __restrict__ A,
                       float* __restrict__ b,
                       const float* __restrict__ kuw,
                       const float* __restrict__ kToUconf,
                       const float* __restrict__ known,
                       const float* __restrict__ kToU,
                       const float* __restrict__ lmbda) {
    int i = blockIdx.x * blockDim.x + threadIdx.x;
    if (i >= NV) return;
    float d = kuw[i] * kToUconf[i] + lmbda[0] * known[i];
    atomicAdd(&A[(size_t)i * NV + i], d);
    b[i] = d * kToU[i];
}

// ---------------------------------------------------------------------------
extern "C" void kernel_launch(void* const* d_in, const int* in_sizes, int n_in,
                              void* d_out, int out_size) {
    // metadata order:
    // 0 height, 1 width, 2 CM_weights, 3 LOC_weights, 4 IU_weights,
    // 5 KU_weights, 6 lmbda, 7 kToUconf, 8 known, 9 kToU,
    // 10 Wcm_row, 11 Wcm_col, 12 Wcm_data, 13 LOC_inInd, 14 LOC_flows,
    // 15 IU_inInd, 16 IU_flows, 17 IU_neighInd
    const float* CM_weights = (const float*)d_in[2];
    const float* LOC_weights = (const float*)d_in[3];
    const float* IU_weights  = (const float*)d_in[4];
    const float* KU_weights  = (const float*)d_in[5];
    const float* lmbda       = (const float*)d_in[6];
    const float* kToUconf    = (const float*)d_in[7];
    const float* known       = (const float*)d_in[8];
    const float* kToU        = (const float*)d_in[9];
    const int*   Wcm_row     = (const int*)d_in[10];
    const int*   Wcm_col     = (const int*)d_in[11];
    const float* Wcm_data    = (const float*)d_in[12];
    const int*   LOC_inInd   = (const int*)d_in[13];
    const float* LOC_flows   = (const float*)d_in[14];
    const int*   IU_inInd    = (const int*)d_in[15];
    const float* IU_flows    = (const float*)d_in[16];
    const int*   IU_neighInd = (const int*)d_in[17];

    float* A = (float*)d_out;              // first N*N floats
    float* b = (float*)d_out + (size_t)NV * NV;

    // Zero the whole output (A + b). Dominant HBM cost of this kernel.
    cudaMemsetAsync(d_out, 0, ((size_t)NV * NV + NV) * sizeof(float), 0);

    k_reset<<<(NV + 255) / 256, 256>>>();
    k_build_cm<<<(NNZCM + 255) / 256, 256>>>(Wcm_row, Wcm_col, Wcm_data, CM_weights);
    k_outer<<<NV, 128>>>(A);
    k_loc<<<(MLOC * 9 + 255) / 256, 256>>>(A, LOC_inInd, LOC_flows, LOC_weights);
    k_iu<<<(MIU * 5 + 255) / 256, 256>>>(A, IU_inInd, IU_flows, IU_neighInd, IU_weights);
    k_diag<<<(NV + 255) / 256, 256>>>(A, b, KU_weights, kToUconf, known, kToU, lmbda);
}